// round 2
// baseline (speedup 1.0000x reference)
#include <cuda_runtime.h>
#include <cuda_bf16.h>
#include <math.h>

#define B_   32
#define NCH  1024
#define NPTS 4096

// winner point index per (batch, channel)
__device__ int g_imp[B_ * NCH];

// ---------------------------------------------------------------------------
// Kernel 1: per-channel argmax over points.
// grid = 128 blocks (32 batches x 4 channel groups), 256 threads.
// Each thread owns ONE channel: W row + 8 independent (best,idx) accumulators
// in registers. x[b] (48KB) lives in shared; reads are warp-broadcast LDS.128,
// so one shared load feeds 32 channels.
// ---------------------------------------------------------------------------
__global__ void __launch_bounds__(256) argmax_kernel(
    const float* __restrict__ x, const float* __restrict__ W)
{
    __shared__ float sx[3 * NPTS];   // 48KB: rows x0, x1, x2 contiguous

    const int b   = blockIdx.x >> 2;
    const int grp = blockIdx.x & 3;

    // cooperative vectorized load of x[b] into shared
    {
        const float4* src = (const float4*)(x + (size_t)b * 3 * NPTS);
        float4* dst = (float4*)sx;
        #pragma unroll
        for (int i = threadIdx.x; i < 3 * NPTS / 4; i += 256) dst[i] = src[i];
    }
    __syncthreads();

    const int c = grp * 256 + threadIdx.x;
    const float w0 = W[c * 3 + 0];
    const float w1 = W[c * 3 + 1];
    const float w2 = W[c * 3 + 2];

    const float* __restrict__ sx0 = sx;
    const float* __restrict__ sx1 = sx + NPTS;
    const float* __restrict__ sx2 = sx + 2 * NPTS;

    float best[8];
    int   bidx[8];
    #pragma unroll
    for (int k = 0; k < 8; k++) { best[k] = -INFINITY; bidx[k] = 0; }

    for (int n = 0; n < NPTS; n += 8) {
        #pragma unroll
        for (int k = 0; k < 8; k++) {
            float f = fmaf(w2, sx2[n + k], fmaf(w1, sx1[n + k], w0 * sx0[n + k]));
            if (f > best[k]) { best[k] = f; bidx[k] = n + k; }
        }
    }

    // merge 8 streams; on equal value prefer lower index (first-occurrence)
    float bv = best[0]; int bi = bidx[0];
    #pragma unroll
    for (int k = 1; k < 8; k++) {
        if (best[k] > bv || (best[k] == bv && bidx[k] < bi)) {
            bv = best[k]; bi = bidx[k];
        }
    }
    g_imp[b * NCH + c] = bi;
}

// ---------------------------------------------------------------------------
// Kernel 2: per-batch counts, entropy, stable counting-sort (imp2).
// grid = 32 blocks, 1024 threads.
// ---------------------------------------------------------------------------
__global__ void __launch_bounds__(1024) sort_entropy_kernel(
    float* __restrict__ out_counts,   // [B, NPTS]
    float* __restrict__ out_imp2,     // [B, NPTS]
    float* __restrict__ out_ent)      // [B]
{
    __shared__ int   scnt[NPTS];
    __shared__ int   hist[NCH + 1];   // values in [0, 1024]
    __shared__ float red[32];
    __shared__ float s_sum;

    const int b = blockIdx.x;
    const int t = threadIdx.x;
    const int lane = t & 31;
    const int wid  = t >> 5;

    // zero
    #pragma unroll
    for (int i = t; i < NPTS; i += 1024) scnt[i] = 0;
    for (int i = t; i < NCH + 1; i += 1024) hist[i] = 0;
    __syncthreads();

    // counts: one winner index per channel
    atomicAdd(&scnt[g_imp[b * NCH + t]], 1);
    __syncthreads();

    // write counts + histogram of count-values
    #pragma unroll
    for (int i = t; i < NPTS; i += 1024) {
        int cv = scnt[i];
        out_counts[b * NPTS + i] = (float)cv;
        atomicAdd(&hist[cv], 1);
    }
    __syncthreads();

    // exclusive prefix sum over hist[0..1024], warp 0 only
    if (wid == 0) {
        int carry = 0;
        for (int ch = 0; ch < 33; ch++) {
            int idx = ch * 32 + lane;
            int v = (idx < NCH + 1) ? hist[idx] : 0;
            int s = v;
            #pragma unroll
            for (int off = 1; off < 32; off <<= 1) {
                int u = __shfl_up_sync(0xffffffffu, s, off);
                if (lane >= off) s += u;
            }
            if (idx < NCH + 1) hist[idx] = s - v + carry;
            carry += __shfl_sync(0xffffffffu, s, 31);
        }
    }
    __syncthreads();

    // ---- entropy (all 1024 threads): matches my_entropy() in fp32 ----
    {
        float part = 0.f;
        #pragma unroll
        for (int i = t; i < NPTS; i += 1024) part += (float)scnt[i] + 1e-6f;
        #pragma unroll
        for (int o = 16; o; o >>= 1) part += __shfl_down_sync(0xffffffffu, part, o);
        if (lane == 0) red[wid] = part;
        __syncthreads();
        if (wid == 0) {
            float v = red[lane];
            #pragma unroll
            for (int o = 16; o; o >>= 1) v += __shfl_down_sync(0xffffffffu, v, o);
            if (lane == 0) s_sum = v;
        }
        __syncthreads();
        const float s = s_sum;
        float part2 = 0.f;
        #pragma unroll
        for (int i = t; i < NPTS; i += 1024) {
            float p = ((float)scnt[i] + 1e-6f) / s;
            part2 += p * log2f(p);
        }
        __syncthreads();   // red[] reuse guard
        #pragma unroll
        for (int o = 16; o; o >>= 1) part2 += __shfl_down_sync(0xffffffffu, part2, o);
        if (lane == 0) red[wid] = part2;
        __syncthreads();
        if (wid == 0) {
            float v = red[lane];
            #pragma unroll
            for (int o = 16; o; o >>= 1) v += __shfl_down_sync(0xffffffffu, v, o);
            if (lane == 0) out_ent[b] = -v / 12.0f;   // log2(4096) = 12
        }
    }
    __syncthreads();

    // ---- stable counting-sort placement: warp 0, ascending n in chunks of 32.
    // rank(n) = start[v] + (#earlier n with same v); within-chunk rank via
    // match_any + popc over lower lanes; group leader bumps the counter.
    if (wid == 0) {
        for (int nb = 0; nb < NPTS; nb += 32) {
            const int n = nb + lane;
            const int v = scnt[n];
            unsigned peers = __match_any_sync(0xffffffffu, v);
            int lrank = __popc(peers & ((1u << lane) - 1u));
            int start = hist[v];                       // warp-broadcast read
            out_imp2[b * NPTS + start + lrank] = (float)n;
            int leader = __ffs(peers) - 1;
            if (lane == leader) hist[v] = start + __popc(peers);
            __syncwarp();
        }
    }
}

// ---------------------------------------------------------------------------
extern "C" void kernel_launch(void* const* d_in, const int* in_sizes, int n_in,
                              void* d_out, int out_size)
{
    const float* x = (const float*)d_in[0];   // [32, 3, 4096]
    const float* W = (const float*)d_in[1];   // [1024, 3]
    float* out = (float*)d_out;

    float* out_x      = out;                                   // 393216
    float* out_counts = out + B_ * 3 * NPTS;                   // 131072
    float* out_imp2   = out_counts + B_ * NPTS;                // 131072
    float* out_ent    = out_imp2 + B_ * NPTS;                  // 32

    // tuple element 0: x passthrough
    cudaMemcpyAsync(out_x, x, (size_t)B_ * 3 * NPTS * sizeof(float),
                    cudaMemcpyDeviceToDevice);

    argmax_kernel<<<B_ * 4, 256>>>(x, W);
    sort_entropy_kernel<<<B_, 1024>>>(out_counts, out_imp2, out_ent);
}

// round 3
// speedup vs baseline: 1.2458x; 1.2458x over previous
#include <cuda_runtime.h>
#include <math.h>

#define B_    32
#define NCH   1024
#define NPTS  4096
#define NSEG  32
#define SEGSZ 128
#define RS    4224   // skewed row stride in floats: 4096 + 32 segs * 4 skew

__device__ int g_imp[B_ * NCH];

typedef unsigned long long ull;
__device__ __forceinline__ ull pk2(float lo, float hi) {
    ull r; asm("mov.b64 %0, {%1,%2};" : "=l"(r) : "f"(lo), "f"(hi)); return r;
}
__device__ __forceinline__ void upk2(ull v, float& lo, float& hi) {
    asm("mov.b64 {%0,%1}, %2;" : "=f"(lo), "=f"(hi) : "l"(v));
}
__device__ __forceinline__ ull mul2_(ull a, ull b) {
    ull r; asm("mul.rn.f32x2 %0,%1,%2;" : "=l"(r) : "l"(a), "l"(b)); return r;
}
__device__ __forceinline__ ull fma2_(ull a, ull b, ull c) {
    ull r; asm("fma.rn.f32x2 %0,%1,%2,%3;" : "=l"(r) : "l"(a), "l"(b), "l"(c)); return r;
}

// ---------------------------------------------------------------------------
// Kernel 1: hierarchical per-channel argmax.
// grid = 128 (32 batches x 4 channel groups), 256 threads, thread = channel.
// Pass 1: packed f32x2 dot products, segment maxima only (32 segs x 128 pts).
// Pass 2: rescan winning segment, bitwise-identical scalar recompute.
// ---------------------------------------------------------------------------
__global__ void __launch_bounds__(256) argmax_kernel(
    const float* __restrict__ x, const float* __restrict__ W)
{
    extern __shared__ float sx[];   // 3 rows x RS floats, skewed

    const int b   = blockIdx.x >> 2;
    const int grp = blockIdx.x & 3;

    // cooperative skewed load of x[b] (48KB logical)
    {
        const float4* src = (const float4*)(x + (size_t)b * 3 * NPTS);
        for (int i4 = threadIdx.x; i4 < 3 * (NPTS / 4); i4 += 256) {
            int row = i4 >> 10;
            int li  = (i4 & 1023) << 2;
            float4 v = src[i4];
            *(float4*)(sx + row * RS + li + ((li >> 7) << 2)) = v;
        }
    }
    __syncthreads();

    const int c = grp * 256 + threadIdx.x;
    const float w0 = W[c * 3 + 0];
    const float w1 = W[c * 3 + 1];
    const float w2 = W[c * 3 + 2];
    const ull w0p = pk2(w0, w0), w1p = pk2(w1, w1), w2p = pk2(w2, w2);

    const float* r0 = sx;
    const float* r1 = sx + RS;
    const float* r2 = sx + 2 * RS;

    float gmax = -INFINITY;
    int   gseg = 0;

    for (int s = 0; s < NSEG; ++s) {
        const float* p0 = r0 + s * 132;   // 128 data + 4 skew per segment
        const float* p1 = r1 + s * 132;
        const float* p2 = r2 + s * 132;

        float2 m0 = {-INFINITY, -INFINITY}, m1 = m0, m2 = m0, m3 = m0;

        #pragma unroll
        for (int i = 0; i < SEGSZ; i += 8) {
            float4 xa = *(const float4*)(p0 + i);
            float4 xb = *(const float4*)(p0 + i + 4);
            float4 ya = *(const float4*)(p1 + i);
            float4 yb = *(const float4*)(p1 + i + 4);
            float4 za = *(const float4*)(p2 + i);
            float4 zb = *(const float4*)(p2 + i + 4);

            ull v0 = fma2_(w2p, pk2(za.x, za.y), fma2_(w1p, pk2(ya.x, ya.y), mul2_(w0p, pk2(xa.x, xa.y))));
            ull v1 = fma2_(w2p, pk2(za.z, za.w), fma2_(w1p, pk2(ya.z, ya.w), mul2_(w0p, pk2(xa.z, xa.w))));
            ull v2 = fma2_(w2p, pk2(zb.x, zb.y), fma2_(w1p, pk2(yb.x, yb.y), mul2_(w0p, pk2(xb.x, xb.y))));
            ull v3 = fma2_(w2p, pk2(zb.z, zb.w), fma2_(w1p, pk2(yb.z, yb.w), mul2_(w0p, pk2(xb.z, xb.w))));

            float a, h;
            upk2(v0, a, h); m0.x = fmaxf(m0.x, a); m0.y = fmaxf(m0.y, h);
            upk2(v1, a, h); m1.x = fmaxf(m1.x, a); m1.y = fmaxf(m1.y, h);
            upk2(v2, a, h); m2.x = fmaxf(m2.x, a); m2.y = fmaxf(m2.y, h);
            upk2(v3, a, h); m3.x = fmaxf(m3.x, a); m3.y = fmaxf(m3.y, h);
        }

        float sm = fmaxf(fmaxf(fmaxf(m0.x, m0.y), fmaxf(m1.x, m1.y)),
                         fmaxf(fmaxf(m2.x, m2.y), fmaxf(m3.x, m3.y)));
        if (sm > gmax) { gmax = sm; gseg = s; }   // strict > keeps earliest segment
    }

    // pass 2: find first index in winning segment with f == gmax
    {
        const float* q0 = r0 + gseg * 132;
        const float* q1 = r1 + gseg * 132;
        const float* q2 = r2 + gseg * 132;
        int fi = SEGSZ;
        #pragma unroll 4
        for (int i = 0; i < SEGSZ; ++i) {
            float f = __fmaf_rn(w2, q2[i], __fmaf_rn(w1, q1[i], __fmul_rn(w0, q0[i])));
            if (f == gmax && i < fi) fi = i;
        }
        g_imp[b * NCH + c] = gseg * SEGSZ + fi;
    }
}

// ---------------------------------------------------------------------------
// Kernel 2: counts, entropy, parallel stable counting-sort (imp2).
// grid = 32 (one per batch), 1024 threads.
// ---------------------------------------------------------------------------
__global__ void __launch_bounds__(1024) sort_entropy_kernel(
    float* __restrict__ out_counts,
    float* __restrict__ out_imp2,
    float* __restrict__ out_ent)
{
    __shared__ int            scnt[NPTS];            // 16KB
    __shared__ int            gstart[NCH + 1];       // 4.1KB (value totals -> scan)
    __shared__ unsigned short ch[(NCH + 1) * 9];     // chunk hist, padded rows (18.4KB)
    __shared__ unsigned short lrk[NPTS];             // local rank within chunk (8KB)
    __shared__ float          red[32];

    const int b    = blockIdx.x;
    const int t    = threadIdx.x;
    const int lane = t & 31;
    const int wid  = t >> 5;

    // A: zero
    #pragma unroll
    for (int i = t; i < NPTS; i += 1024) scnt[i] = 0;
    for (int i = t; i < (NCH + 1) * 9; i += 1024) ch[i] = 0;
    __syncthreads();

    // B: histogram of winner indices
    atomicAdd(&scnt[g_imp[b * NCH + t]], 1);
    __syncthreads();

    // C: write counts + entropy partial (sum of counts+eps is analytically known)
    const float inv_s = 1.0f / (1024.0f + 4096.0f * 1e-6f);
    float part2 = 0.f;
    #pragma unroll
    for (int i = t; i < NPTS; i += 1024) {
        int cv = scnt[i];
        out_counts[b * NPTS + i] = (float)cv;
        float p = ((float)cv + 1e-6f) * inv_s;
        part2 += p * __log2f(p);
    }

    // D: per-chunk stable local ranks (8 warps, chunk = 512 points each)
    if (wid < 8) {
        #pragma unroll 1
        for (int r = 0; r < 16; ++r) {
            int n = (wid << 9) + (r << 5) + lane;
            int v = scnt[n];
            unsigned peers = __match_any_sync(0xffffffffu, v);
            int lr = __popc(peers & ((1u << lane) - 1u));
            int base = ch[v * 9 + wid];
            lrk[n] = (unsigned short)(base + lr);
            if (lane == (__ffs(peers) - 1))
                ch[v * 9 + wid] = (unsigned short)(base + __popc(peers));
            __syncwarp();
        }
    }
    __syncthreads();

    // E: entropy reduction
    #pragma unroll
    for (int o = 16; o; o >>= 1) part2 += __shfl_down_sync(0xffffffffu, part2, o);
    if (lane == 0) red[wid] = part2;
    __syncthreads();
    if (wid == 0) {
        float v = red[lane];
        #pragma unroll
        for (int o = 16; o; o >>= 1) v += __shfl_down_sync(0xffffffffu, v, o);
        if (lane == 0) out_ent[b] = -v / 12.0f;     // log2(4096) = 12
    }

    // F: per-value prefix across chunks (thread per value), totals -> gstart
    for (int v = t; v < NCH + 1; v += 1024) {
        int run = 0;
        #pragma unroll
        for (int w = 0; w < 8; ++w) {
            int cc = ch[v * 9 + w];
            ch[v * 9 + w] = (unsigned short)run;
            run += cc;
        }
        gstart[v] = run;
    }
    __syncthreads();

    // G: exclusive scan of value totals (warp 0)
    if (wid == 0) {
        int carry = 0;
        for (int chk = 0; chk < 33; ++chk) {
            int idx = chk * 32 + lane;
            int v = (idx < NCH + 1) ? gstart[idx] : 0;
            int s = v;
            #pragma unroll
            for (int off = 1; off < 32; off <<= 1) {
                int u = __shfl_up_sync(0xffffffffu, s, off);
                if (lane >= off) s += u;
            }
            if (idx < NCH + 1) gstart[idx] = s - v + carry;
            carry += __shfl_sync(0xffffffffu, s, 31);
        }
    }
    __syncthreads();

    // H: scatter final ranks
    #pragma unroll
    for (int n = t; n < NPTS; n += 1024) {
        int v = scnt[n];
        int rank = gstart[v] + (int)ch[v * 9 + (n >> 9)] + (int)lrk[n];
        out_imp2[b * NPTS + rank] = (float)n;
    }
}

// ---------------------------------------------------------------------------
extern "C" void kernel_launch(void* const* d_in, const int* in_sizes, int n_in,
                              void* d_out, int out_size)
{
    const float* x = (const float*)d_in[0];   // [32, 3, 4096]
    const float* W = (const float*)d_in[1];   // [1024, 3]
    float* out = (float*)d_out;

    float* out_x      = out;
    float* out_counts = out + B_ * 3 * NPTS;
    float* out_imp2   = out_counts + B_ * NPTS;
    float* out_ent    = out_imp2 + B_ * NPTS;

    cudaMemcpyAsync(out_x, x, (size_t)B_ * 3 * NPTS * sizeof(float),
                    cudaMemcpyDeviceToDevice);

    const int smem = 3 * RS * sizeof(float);   // 50688 bytes
    cudaFuncSetAttribute(argmax_kernel,
                         cudaFuncAttributeMaxDynamicSharedMemorySize, smem);
    argmax_kernel<<<B_ * 4, 256, smem>>>(x, W);
    sort_entropy_kernel<<<B_, 1024>>>(out_counts, out_imp2, out_ent);
}

// round 4
// speedup vs baseline: 1.4788x; 1.1870x over previous
#include <cuda_runtime.h>
#include <math.h>

#define B_    32
#define NCH   1024
#define NPTS  4096
#define QSPL  4          // point-quarter splits
#define QPTS  1024       // points per block
#define NSEG  16         // segments per block
#define SEGSZ 64
#define SSTR  68         // segment stride in floats (64 data + 4 skew, 16B aligned)
#define ROWF  (NSEG * SSTR)   // 1088 floats per coordinate row

// packed argmax partials: [q][b][c] -> (ordf(max)<<32) | (4095 - idx)
__device__ unsigned long long g_part[QSPL * B_ * NCH];

typedef unsigned long long ull;

__device__ __forceinline__ ull mul2_(ull a, ull b) {
    ull r; asm("mul.rn.f32x2 %0,%1,%2;" : "=l"(r) : "l"(a), "l"(b)); return r;
}
__device__ __forceinline__ ull fma2_(ull a, ull b, ull c) {
    ull r; asm("fma.rn.f32x2 %0,%1,%2,%3;" : "=l"(r) : "l"(a), "l"(b), "l"(c)); return r;
}
__device__ __forceinline__ void upk2(ull v, float& lo, float& hi) {
    asm("mov.b64 {%0,%1}, %2;" : "=f"(lo), "=f"(hi) : "l"(v));
}
__device__ __forceinline__ ull pkw(float w) {
    ull r; asm("mov.b64 %0, {%1,%1};" : "=l"(r) : "f"(w)); return r;
}
__device__ __forceinline__ unsigned int ordf(float f) {
    unsigned int u = __float_as_uint(f);
    return (u & 0x80000000u) ? ~u : (u | 0x80000000u);
}

// ---------------------------------------------------------------------------
// Kernel 1: partial hierarchical argmax over a 1024-point quarter.
// grid = 512 (32 b x 4 grp x 4 q), 256 threads, thread = channel.
// ---------------------------------------------------------------------------
__global__ void __launch_bounds__(256) argmax_kernel(
    const float* __restrict__ x, const float* __restrict__ W)
{
    __shared__ float sx[3 * ROWF];   // 13056 B, skewed

    const int bx  = blockIdx.x;
    const int b   = bx >> 4;
    const int grp = (bx >> 2) & 3;
    const int q   = bx & 3;

    // cooperative skewed load of quarter q of x[b]
    {
        const float* src = x + (size_t)b * 3 * NPTS + q * QPTS;
        for (int i4 = threadIdx.x; i4 < 3 * (QPTS / 4); i4 += 256) {
            int row = i4 / (QPTS / 4);
            int li  = (i4 % (QPTS / 4)) << 2;
            float4 v = *(const float4*)(src + row * NPTS + li);
            *(float4*)(sx + row * ROWF + (li >> 6) * SSTR + (li & 63)) = v;
        }
    }
    __syncthreads();

    const int c  = grp * 256 + threadIdx.x;
    const float w0 = W[c * 3 + 0];
    const float w1 = W[c * 3 + 1];
    const float w2 = W[c * 3 + 2];
    const ull w0p = pkw(w0), w1p = pkw(w1), w2p = pkw(w2);

    float gmax = -INFINITY;
    int   gseg = 0;

    #pragma unroll 1
    for (int s = 0; s < NSEG; ++s) {
        const float* p0 = sx + s * SSTR;
        const float* p1 = p0 + ROWF;
        const float* p2 = p0 + 2 * ROWF;

        float m0 = -INFINITY, m1 = m0, m2 = m0, m3 = m0,
              m4 = m0, m5 = m0, m6 = m0, m7 = m0;

        #pragma unroll
        for (int i = 0; i < SEGSZ; i += 8) {
            ulonglong2 xa = *(const ulonglong2*)(p0 + i);
            ulonglong2 xb = *(const ulonglong2*)(p0 + i + 4);
            ulonglong2 ya = *(const ulonglong2*)(p1 + i);
            ulonglong2 yb = *(const ulonglong2*)(p1 + i + 4);
            ulonglong2 za = *(const ulonglong2*)(p2 + i);
            ulonglong2 zb = *(const ulonglong2*)(p2 + i + 4);

            ull v0 = fma2_(w2p, za.x, fma2_(w1p, ya.x, mul2_(w0p, xa.x)));
            ull v1 = fma2_(w2p, za.y, fma2_(w1p, ya.y, mul2_(w0p, xa.y)));
            ull v2 = fma2_(w2p, zb.x, fma2_(w1p, yb.x, mul2_(w0p, xb.x)));
            ull v3 = fma2_(w2p, zb.y, fma2_(w1p, yb.y, mul2_(w0p, xb.y)));

            float a, h;
            upk2(v0, a, h); m0 = fmaxf(m0, a); m1 = fmaxf(m1, h);
            upk2(v1, a, h); m2 = fmaxf(m2, a); m3 = fmaxf(m3, h);
            upk2(v2, a, h); m4 = fmaxf(m4, a); m5 = fmaxf(m5, h);
            upk2(v3, a, h); m6 = fmaxf(m6, a); m7 = fmaxf(m7, h);
        }

        float sm = fmaxf(fmaxf(fmaxf(m0, m1), fmaxf(m2, m3)),
                         fmaxf(fmaxf(m4, m5), fmaxf(m6, m7)));
        if (sm > gmax) { gmax = sm; gseg = s; }   // strict >: earliest segment
    }

    // pass 2: first index in winning segment with bitwise-identical recompute
    {
        const float* q0 = sx + gseg * SSTR;
        const float* q1 = q0 + ROWF;
        const float* q2 = q0 + 2 * ROWF;
        int fi = SEGSZ;
        #pragma unroll 4
        for (int i = 0; i < SEGSZ; ++i) {
            float f = __fmaf_rn(w2, q2[i], __fmaf_rn(w1, q1[i], __fmul_rn(w0, q0[i])));
            if (f == gmax && i < fi) fi = i;
        }
        int gidx = q * QPTS + gseg * SEGSZ + fi;
        g_part[(q * B_ + b) * NCH + c] =
            ((ull)ordf(gmax) << 32) | (ull)(unsigned)(4095 - gidx);
    }
}

// ---------------------------------------------------------------------------
// Kernel 2: merge partials, counts, entropy, parallel stable counting sort.
// grid = 32 (one per batch), 1024 threads.
// ---------------------------------------------------------------------------
__global__ void __launch_bounds__(1024) sort_entropy_kernel(
    float* __restrict__ out_counts,
    float* __restrict__ out_imp2,
    float* __restrict__ out_ent)
{
    __shared__ int            scnt[NPTS];
    __shared__ int            gstart[NCH + 1];
    __shared__ unsigned short ch[(NCH + 1) * 9];
    __shared__ unsigned short lrk[NPTS];
    __shared__ float          red[32];

    const int b    = blockIdx.x;
    const int t    = threadIdx.x;
    const int lane = t & 31;
    const int wid  = t >> 5;

    // A: zero
    #pragma unroll
    for (int i = t; i < NPTS; i += 1024) scnt[i] = 0;
    for (int i = t; i < (NCH + 1) * 9; i += 1024) ch[i] = 0;
    __syncthreads();

    // B: merge 4 quarter-partials for channel t, histogram winner index
    {
        ull k0 = g_part[(0 * B_ + b) * NCH + t];
        ull k1 = g_part[(1 * B_ + b) * NCH + t];
        ull k2 = g_part[(2 * B_ + b) * NCH + t];
        ull k3 = g_part[(3 * B_ + b) * NCH + t];
        ull kk = max(max(k0, k1), max(k2, k3));
        int idx = 4095 - (int)(kk & 0xFFFFFFFFull);
        atomicAdd(&scnt[idx], 1);
    }
    __syncthreads();

    // C: write counts + entropy partial (sum of counts+eps analytically known)
    const float inv_s = 1.0f / (1024.0f + 4096.0f * 1e-6f);
    float part2 = 0.f;
    #pragma unroll
    for (int i = t; i < NPTS; i += 1024) {
        int cv = scnt[i];
        out_counts[b * NPTS + i] = (float)cv;
        float p = ((float)cv + 1e-6f) * inv_s;
        part2 += p * __log2f(p);
    }

    // D: per-chunk stable local ranks (8 warps, chunk = 512 points)
    if (wid < 8) {
        #pragma unroll 1
        for (int r = 0; r < 16; ++r) {
            int n = (wid << 9) + (r << 5) + lane;
            int v = scnt[n];
            unsigned peers = __match_any_sync(0xffffffffu, v);
            int lr = __popc(peers & ((1u << lane) - 1u));
            int base = ch[v * 9 + wid];
            lrk[n] = (unsigned short)(base + lr);
            if (lane == (__ffs(peers) - 1))
                ch[v * 9 + wid] = (unsigned short)(base + __popc(peers));
            __syncwarp();
        }
    }
    __syncthreads();

    // E: entropy reduction
    #pragma unroll
    for (int o = 16; o; o >>= 1) part2 += __shfl_down_sync(0xffffffffu, part2, o);
    if (lane == 0) red[wid] = part2;
    __syncthreads();
    if (wid == 0) {
        float v = red[lane];
        #pragma unroll
        for (int o = 16; o; o >>= 1) v += __shfl_down_sync(0xffffffffu, v, o);
        if (lane == 0) out_ent[b] = -v / 12.0f;     // log2(4096) = 12
    }

    // F: per-value prefix across chunks; totals -> gstart
    for (int v = t; v < NCH + 1; v += 1024) {
        int run = 0;
        #pragma unroll
        for (int w = 0; w < 8; ++w) {
            int cc = ch[v * 9 + w];
            ch[v * 9 + w] = (unsigned short)run;
            run += cc;
        }
        gstart[v] = run;
    }
    __syncthreads();

    // G: exclusive scan of value totals (warp 0)
    if (wid == 0) {
        int carry = 0;
        for (int chk = 0; chk < 33; ++chk) {
            int idx = chk * 32 + lane;
            int v = (idx < NCH + 1) ? gstart[idx] : 0;
            int s = v;
            #pragma unroll
            for (int off = 1; off < 32; off <<= 1) {
                int u = __shfl_up_sync(0xffffffffu, s, off);
                if (lane >= off) s += u;
            }
            if (idx < NCH + 1) gstart[idx] = s - v + carry;
            carry += __shfl_sync(0xffffffffu, s, 31);
        }
    }
    __syncthreads();

    // H: scatter final ranks
    #pragma unroll
    for (int n = t; n < NPTS; n += 1024) {
        int v = scnt[n];
        int rank = gstart[v] + (int)ch[v * 9 + (n >> 9)] + (int)lrk[n];
        out_imp2[b * NPTS + rank] = (float)n;
    }
}

// ---------------------------------------------------------------------------
extern "C" void kernel_launch(void* const* d_in, const int* in_sizes, int n_in,
                              void* d_out, int out_size)
{
    const float* x = (const float*)d_in[0];   // [32, 3, 4096]
    const float* W = (const float*)d_in[1];   // [1024, 3]
    float* out = (float*)d_out;

    float* out_x      = out;
    float* out_counts = out + B_ * 3 * NPTS;
    float* out_imp2   = out_counts + B_ * NPTS;
    float* out_ent    = out_imp2 + B_ * NPTS;

    cudaMemcpyAsync(out_x, x, (size_t)B_ * 3 * NPTS * sizeof(float),
                    cudaMemcpyDeviceToDevice);

    argmax_kernel<<<B_ * 4 * QSPL, 256>>>(x, W);
    sort_entropy_kernel<<<B_, 1024>>>(out_counts, out_imp2, out_ent);
}

// round 5
// speedup vs baseline: 1.8930x; 1.2801x over previous
#include <cuda_runtime.h>
#include <math.h>

#define B_    32
#define NCH   1024
#define NPTS  4096
#define QS    16         // point splits
#define QP    256        // points per block
#define SEGSZ 32
#define NSEG  8
#define SSTR  36         // 32 data + 4 skew floats (16B-aligned stride)
#define ROWF  (NSEG * SSTR)   // 288 floats per coord row

// packed argmax partials: [q][b][c] -> (ordf(max)<<32) | (4095 - idx)
__device__ unsigned long long g_part[QS * B_ * NCH];

typedef unsigned long long ull;

__device__ __forceinline__ ull mul2_(ull a, ull b) {
    ull r; asm("mul.rn.f32x2 %0,%1,%2;" : "=l"(r) : "l"(a), "l"(b)); return r;
}
__device__ __forceinline__ ull fma2_(ull a, ull b, ull c) {
    ull r; asm("fma.rn.f32x2 %0,%1,%2,%3;" : "=l"(r) : "l"(a), "l"(b), "l"(c)); return r;
}
__device__ __forceinline__ void upk2(ull v, float& lo, float& hi) {
    asm("mov.b64 {%0,%1}, %2;" : "=f"(lo), "=f"(hi) : "l"(v));
}
__device__ __forceinline__ ull pkw(float w) {
    ull r; asm("mov.b64 %0, {%1,%1};" : "=l"(r) : "f"(w)); return r;
}
__device__ __forceinline__ unsigned int ordf(float f) {
    unsigned int u = __float_as_uint(f);
    return (u & 0x80000000u) ? ~u : (u | 0x80000000u);
}

// ---------------------------------------------------------------------------
// Kernel 1: partial argmax, 4 channels per thread.
// grid = 512 (32 b x 16 q), 256 threads. Also writes the x passthrough.
// ---------------------------------------------------------------------------
__global__ void __launch_bounds__(256, 3) argmax_kernel(
    const float* __restrict__ x, const float* __restrict__ W,
    float* __restrict__ out_x)
{
    __shared__ __align__(16) float sx[3 * ROWF];

    const int b = blockIdx.x >> 4;
    const int q = blockIdx.x & 15;

    const float* src = x     + (size_t)b * 3 * NPTS + q * QP;
    float*       dst = out_x + (size_t)b * 3 * NPTS + q * QP;
    {
        int i = threadIdx.x;
        if (i < 192) {                       // 3 rows x 64 float4
            int row = i >> 6;
            int li  = (i & 63) << 2;
            float4 v = *(const float4*)(src + row * NPTS + li);
            *(float4*)(sx + row * ROWF + (li >> 5) * SSTR + (li & 31)) = v;
            *(float4*)(dst + row * NPTS + li) = v;   // fold x passthrough
        }
    }
    __syncthreads();

    const int t = threadIdx.x;
    float w0[4], w1[4], w2[4];
    ull   W0[4], W1[4], W2[4];
    #pragma unroll
    for (int s = 0; s < 4; ++s) {
        int c = s * 256 + t;
        w0[s] = W[c * 3 + 0]; w1[s] = W[c * 3 + 1]; w2[s] = W[c * 3 + 2];
        W0[s] = pkw(w0[s]);   W1[s] = pkw(w1[s]);   W2[s] = pkw(w2[s]);
    }

    float gmax[4]; int gseg[4];
    #pragma unroll
    for (int s = 0; s < 4; ++s) { gmax[s] = -INFINITY; gseg[s] = 0; }

    #pragma unroll 1
    for (int sg = 0; sg < NSEG; ++sg) {
        const float* a0 = sx + sg * SSTR;
        const float* a1 = a0 + ROWF;
        const float* a2 = a0 + 2 * ROWF;

        float m[4][4];
        #pragma unroll
        for (int c = 0; c < 4; ++c)
            m[c][0] = m[c][1] = m[c][2] = m[c][3] = -INFINITY;

        #pragma unroll
        for (int i = 0; i < SEGSZ; i += 4) {
            ulonglong2 xx = *(const ulonglong2*)(a0 + i);
            ulonglong2 yy = *(const ulonglong2*)(a1 + i);
            ulonglong2 zz = *(const ulonglong2*)(a2 + i);
            #pragma unroll
            for (int c = 0; c < 4; ++c) {
                ull vlo = fma2_(W2[c], zz.x, fma2_(W1[c], yy.x, mul2_(W0[c], xx.x)));
                ull vhi = fma2_(W2[c], zz.y, fma2_(W1[c], yy.y, mul2_(W0[c], xx.y)));
                float f0, f1, f2, f3;
                upk2(vlo, f0, f1); upk2(vhi, f2, f3);
                m[c][0] = fmaxf(m[c][0], f0); m[c][1] = fmaxf(m[c][1], f1);
                m[c][2] = fmaxf(m[c][2], f2); m[c][3] = fmaxf(m[c][3], f3);
            }
        }
        #pragma unroll
        for (int c = 0; c < 4; ++c) {
            float sm = fmaxf(fmaxf(m[c][0], m[c][1]), fmaxf(m[c][2], m[c][3]));
            if (sm > gmax[c]) { gmax[c] = sm; gseg[c] = sg; }  // strict >: earliest seg
        }
    }

    // pass 2: vectorized rescan of winning segment; descending-index SEL chain
    // with bitwise-identical packed recompute -> exact first-index semantics.
    #pragma unroll
    for (int c = 0; c < 4; ++c) {
        const float gm = gmax[c];
        const float* a0 = sx + gseg[c] * SSTR;
        const float* a1 = a0 + ROWF;
        const float* a2 = a0 + 2 * ROWF;
        int fi = 0;
        #pragma unroll
        for (int k = SEGSZ - 4; k >= 0; k -= 4) {
            ulonglong2 xx = *(const ulonglong2*)(a0 + k);
            ulonglong2 yy = *(const ulonglong2*)(a1 + k);
            ulonglong2 zz = *(const ulonglong2*)(a2 + k);
            ull vlo = fma2_(W2[c], zz.x, fma2_(W1[c], yy.x, mul2_(W0[c], xx.x)));
            ull vhi = fma2_(W2[c], zz.y, fma2_(W1[c], yy.y, mul2_(W0[c], xx.y)));
            float f0, f1, f2, f3;
            upk2(vlo, f0, f1); upk2(vhi, f2, f3);
            fi = (f3 == gm) ? k + 3 : fi;
            fi = (f2 == gm) ? k + 2 : fi;
            fi = (f1 == gm) ? k + 1 : fi;
            fi = (f0 == gm) ? k     : fi;
        }
        int gidx = q * QP + gseg[c] * SEGSZ + fi;
        g_part[((size_t)q * B_ + b) * NCH + c * 256 + t] =
            ((ull)ordf(gm) << 32) | (ull)(unsigned)(4095 - gidx);
    }
}

// ---------------------------------------------------------------------------
// Kernel 2: merge 16 partials, counts, entropy, parallel stable counting sort.
// grid = 32, 1024 threads, 63.5KB dynamic smem.
// ---------------------------------------------------------------------------
__global__ void __launch_bounds__(1024) sort_entropy_kernel(
    float* __restrict__ out_counts,
    float* __restrict__ out_imp2,
    float* __restrict__ out_ent)
{
    extern __shared__ __align__(16) char smem_raw[];
    int*            scnt   = (int*)smem_raw;                          // 16384 B
    int*            gstart = (int*)(smem_raw + 16384);                // 4104 B (1025 ints)
    unsigned short* chh    = (unsigned short*)(smem_raw + 20488);     // 34852 B (1025*17 u16, padded)
    unsigned short* lrk    = (unsigned short*)(smem_raw + 55340);     // 8192 B
    __shared__ float red[32];
    __shared__ int   ired[32];

    const int b    = blockIdx.x;
    const int t    = threadIdx.x;
    const int lane = t & 31;
    const int wid  = t >> 5;

    // A: zero
    #pragma unroll
    for (int i = t; i < NPTS; i += 1024) scnt[i] = 0;
    for (int i = t; i < 8713; i += 1024) ((unsigned*)chh)[i] = 0;
    __syncthreads();

    // B: merge 16 quarter-partials for channel t, histogram winner index
    {
        ull kk = g_part[(size_t)b * NCH + t];
        #pragma unroll
        for (int qq = 1; qq < QS; ++qq) {
            ull k2 = g_part[((size_t)qq * B_ + b) * NCH + t];
            kk = kk > k2 ? kk : k2;
        }
        atomicAdd(&scnt[4095 - (int)(unsigned)kk], 1);
    }
    __syncthreads();

    // C: write counts (float4) + entropy partial (sum analytically = 1024+4096e-6)
    const float inv_s = 1.0f / (1024.0f + 4096.0f * 1e-6f);
    float part2;
    {
        int4 cv = ((const int4*)scnt)[t];
        float4 cf = make_float4((float)cv.x, (float)cv.y, (float)cv.z, (float)cv.w);
        ((float4*)(out_counts + (size_t)b * NPTS))[t] = cf;
        float p0 = (cf.x + 1e-6f) * inv_s, p1 = (cf.y + 1e-6f) * inv_s;
        float p2 = (cf.z + 1e-6f) * inv_s, p3 = (cf.w + 1e-6f) * inv_s;
        part2 = p0 * __log2f(p0) + p1 * __log2f(p1)
              + p2 * __log2f(p2) + p3 * __log2f(p3);
    }

    // D: per-chunk stable local ranks (16 warps, chunk = 256 pts, 8 rounds)
    if (wid < 16) {
        #pragma unroll 1
        for (int r = 0; r < 8; ++r) {
            int n = (wid << 8) + (r << 5) + lane;
            int v = scnt[n];
            unsigned peers = __match_any_sync(0xffffffffu, v);
            int lr = __popc(peers & ((1u << lane) - 1u));
            int base = chh[v * 17 + wid];
            lrk[n] = (unsigned short)(base + lr);
            if (lane == (__ffs(peers) - 1))
                chh[v * 17 + wid] = (unsigned short)(base + __popc(peers));
            __syncwarp();
        }
    }
    __syncthreads();

    // E: entropy reduction (warp-0 finish overlaps F)
    #pragma unroll
    for (int o = 16; o; o >>= 1) part2 += __shfl_down_sync(0xffffffffu, part2, o);
    if (lane == 0) red[wid] = part2;
    __syncthreads();
    if (wid == 0) {
        float v = red[lane];
        #pragma unroll
        for (int o = 16; o; o >>= 1) v += __shfl_down_sync(0xffffffffu, v, o);
        if (lane == 0) out_ent[b] = -v * (1.0f / 12.0f);   // log2(4096)=12
    }

    // F: per-value prefix across 16 chunks (thread t <-> value t); totals in reg
    int tot;
    {
        int run = 0;
        #pragma unroll
        for (int w = 0; w < 16; ++w) {
            int cc = chh[t * 17 + w];
            chh[t * 17 + w] = (unsigned short)run;
            run += cc;
        }
        tot = run;
        if (t == 0) {    // value 1024 (all channels same point)
            int r2 = 0;
            #pragma unroll
            for (int w = 0; w < 16; ++w) {
                int cc = chh[1024 * 17 + w];
                chh[1024 * 17 + w] = (unsigned short)r2;
                r2 += cc;
            }
            gstart[1024] = 4096 - r2;
        }
    }

    // G: parallel exclusive scan of value totals (0..1023)
    int incl = tot;
    #pragma unroll
    for (int o = 1; o < 32; o <<= 1) {
        int u = __shfl_up_sync(0xffffffffu, incl, o);
        if (lane >= o) incl += u;
    }
    if (lane == 31) ired[wid] = incl;
    __syncthreads();
    if (wid == 0) {
        int v = ired[lane];
        int sc = v;
        #pragma unroll
        for (int o = 1; o < 32; o <<= 1) {
            int u = __shfl_up_sync(0xffffffffu, sc, o);
            if (lane >= o) sc += u;
        }
        ired[lane] = sc - v;    // exclusive warp bases
    }
    __syncthreads();
    gstart[t] = incl - tot + ired[wid];
    __syncthreads();

    // H: scatter final ranks
    #pragma unroll
    for (int n = t; n < NPTS; n += 1024) {
        int v = scnt[n];
        int rank = gstart[v] + (int)chh[v * 17 + (n >> 8)] + (int)lrk[n];
        out_imp2[(size_t)b * NPTS + rank] = (float)n;
    }
}

// ---------------------------------------------------------------------------
extern "C" void kernel_launch(void* const* d_in, const int* in_sizes, int n_in,
                              void* d_out, int out_size)
{
    const float* x = (const float*)d_in[0];   // [32, 3, 4096]
    const float* W = (const float*)d_in[1];   // [1024, 3]
    float* out = (float*)d_out;

    float* out_x      = out;
    float* out_counts = out + B_ * 3 * NPTS;
    float* out_imp2   = out_counts + B_ * NPTS;
    float* out_ent    = out_imp2 + B_ * NPTS;

    const int SORT_SMEM = 63552;
    cudaFuncSetAttribute(sort_entropy_kernel,
                         cudaFuncAttributeMaxDynamicSharedMemorySize, SORT_SMEM);

    argmax_kernel<<<B_ * QS, 256>>>(x, W, out_x);
    sort_entropy_kernel<<<B_, 1024, SORT_SMEM>>>(out_counts, out_imp2, out_ent);
}